// round 1
// baseline (speedup 1.0000x reference)
#include <cuda_runtime.h>
#include <math.h>

// Problem constants (fixed by the reference: B=2, S=2048, D=1024, F=4096, E=8, top-2)
#define T_TOK 4096
#define D_DIM 1024
#define F_DIM 4096
#define E_NUM 8

// GEMM tiling
#define BM 64
#define BN 64
#define BK 16

// ---------------- scratch (device globals: no allocations allowed) ----------
__device__ int   g_sel[T_TOK * 2];          // selected expert ids per token
__device__ float g_wt [T_TOK * 2];          // renormalized routing weights
__device__ int   g_cnt[E_NUM];              // tokens per expert
__device__ int   g_tok[E_NUM * T_TOK];      // gathered token ids   (stride T per expert)
__device__ float g_gw [E_NUM * T_TOK];      // gathered weights
__device__ float g_H  [(size_t)T_TOK * F_DIM]; // intermediate H (reused per expert), 64 MB

// ---------------- router: logits -> softmax -> top2 -> renorm ---------------
__global__ void router_kernel(const float* __restrict__ x,
                              const float* __restrict__ gatew)
{
    int warp = threadIdx.x >> 5;
    int lane = threadIdx.x & 31;
    int t = blockIdx.x * 4 + warp;
    if (t >= T_TOK) return;
    const float* xr = x + (size_t)t * D_DIM;

    float acc[E_NUM];
#pragma unroll
    for (int e = 0; e < E_NUM; e++) acc[e] = 0.f;

    for (int d = lane; d < D_DIM; d += 32) {
        float xv = xr[d];
#pragma unroll
        for (int e = 0; e < E_NUM; e++)
            acc[e] = fmaf(xv, gatew[e * D_DIM + d], acc[e]);
    }
#pragma unroll
    for (int e = 0; e < E_NUM; e++) {
#pragma unroll
        for (int off = 16; off; off >>= 1)
            acc[e] += __shfl_xor_sync(0xffffffffu, acc[e], off);
    }
    if (lane == 0) {
        float m = acc[0];
#pragma unroll
        for (int e = 1; e < E_NUM; e++) m = fmaxf(m, acc[e]);
        float p[E_NUM];
#pragma unroll
        for (int e = 0; e < E_NUM; e++) p[e] = expf(acc[e] - m);
        // top-2 (first occurrence wins on ties, matching jax.lax.top_k)
        int e0 = 0;
#pragma unroll
        for (int e = 1; e < E_NUM; e++) if (p[e] > p[e0]) e0 = e;
        int e1 = (e0 == 0) ? 1 : 0;
#pragma unroll
        for (int e = 0; e < E_NUM; e++) {
            if (e == e0) continue;
            if (p[e] > p[e1]) e1 = e;
        }
        float s = p[e0] + p[e1];
        g_sel[t * 2 + 0] = e0;
        g_sel[t * 2 + 1] = e1;
        g_wt [t * 2 + 0] = p[e0] / s;
        g_wt [t * 2 + 1] = p[e1] / s;
    }
}

// ---------------- deterministic per-expert gather ----------------------------
__global__ void bucket_kernel()
{
    int e = threadIdx.x;
    if (e >= E_NUM) return;
    int n = 0;
    for (int t = 0; t < T_TOK; t++) {
#pragma unroll
        for (int k = 0; k < 2; k++) {
            if (g_sel[t * 2 + k] == e) {
                g_tok[e * T_TOK + n] = t;
                g_gw [e * T_TOK + n] = g_wt[t * 2 + k];
                n++;
            }
        }
    }
    g_cnt[e] = n;
}

// ---------------- GEMM1: H = silu(X W1^T) * (X W3^T), gathered rows ---------
__global__ __launch_bounds__(256)
void gemm1_kernel(const float* __restrict__ x,
                  const float* __restrict__ w1,
                  const float* __restrict__ w3,
                  int e)
{
    int n_e = g_cnt[e];
    int rowBase = blockIdx.y * BM;
    if (rowBase >= n_e) return;
    const float* W1 = w1 + (size_t)e * F_DIM * D_DIM;
    const float* W3 = w3 + (size_t)e * F_DIM * D_DIM;
    int colBase = blockIdx.x * BN;

    __shared__ float As [BK][BM];
    __shared__ float B1s[BK][BN];
    __shared__ float B3s[BK][BN];
    __shared__ int   toks[BM];

    int tid = threadIdx.x;
    if (tid < BM) {
        int r = rowBase + tid;
        toks[tid] = g_tok[e * T_TOK + min(r, n_e - 1)];
    }
    __syncthreads();

    // loader mapping: 256 threads -> (lm = tid/4 in [0,64), lk = (tid%4)*4)
    int lm = tid >> 2;
    int lk = (tid & 3) * 4;
    const float* xrow  = x  + (size_t)toks[lm] * D_DIM + lk;
    const float* w1row = W1 + (size_t)(colBase + lm) * D_DIM + lk;
    const float* w3row = W3 + (size_t)(colBase + lm) * D_DIM + lk;

    int ty4 = (tid >> 4) * 4;
    int tx4 = (tid & 15) * 4;

    float acc1[4][4] = {};
    float acc3[4][4] = {};

    for (int k0 = 0; k0 < D_DIM; k0 += BK) {
        float4 av  = *(const float4*)(xrow  + k0);
        float4 b1v = *(const float4*)(w1row + k0);
        float4 b3v = *(const float4*)(w3row + k0);
        As [lk + 0][lm] = av.x;  As [lk + 1][lm] = av.y;
        As [lk + 2][lm] = av.z;  As [lk + 3][lm] = av.w;
        B1s[lk + 0][lm] = b1v.x; B1s[lk + 1][lm] = b1v.y;
        B1s[lk + 2][lm] = b1v.z; B1s[lk + 3][lm] = b1v.w;
        B3s[lk + 0][lm] = b3v.x; B3s[lk + 1][lm] = b3v.y;
        B3s[lk + 2][lm] = b3v.z; B3s[lk + 3][lm] = b3v.w;
        __syncthreads();

#pragma unroll
        for (int k = 0; k < BK; k++) {
            float4 a  = *(const float4*)&As [k][ty4];
            float4 b1 = *(const float4*)&B1s[k][tx4];
            float4 b3 = *(const float4*)&B3s[k][tx4];
            float avx[4]  = {a.x,  a.y,  a.z,  a.w};
            float b1x[4]  = {b1.x, b1.y, b1.z, b1.w};
            float b3x[4]  = {b3.x, b3.y, b3.z, b3.w};
#pragma unroll
            for (int i = 0; i < 4; i++)
#pragma unroll
                for (int j = 0; j < 4; j++) {
                    acc1[i][j] = fmaf(avx[i], b1x[j], acc1[i][j]);
                    acc3[i][j] = fmaf(avx[i], b3x[j], acc3[i][j]);
                }
        }
        __syncthreads();
    }

#pragma unroll
    for (int i = 0; i < 4; i++) {
        int r = rowBase + ty4 + i;
        if (r >= n_e) continue;
        float* h = g_H + (size_t)r * F_DIM + colBase + tx4;
#pragma unroll
        for (int j = 0; j < 4; j++) {
            float v1 = acc1[i][j];
            float v3 = acc3[i][j];
            float sig = 1.f / (1.f + expf(-v1));
            h[j] = v1 * sig * v3;
        }
    }
}

// ---------------- GEMM2: out[tok] += gw * (H W2^T) ---------------------------
__global__ __launch_bounds__(256)
void gemm2_kernel(const float* __restrict__ w2,
                  float* __restrict__ out,
                  int e)
{
    int n_e = g_cnt[e];
    int rowBase = blockIdx.y * BM;
    if (rowBase >= n_e) return;
    const float* W2 = w2 + (size_t)e * (size_t)D_DIM * F_DIM;
    int colBase = blockIdx.x * BN;  // over D

    __shared__ float As[BK][BM];
    __shared__ float Bs[BK][BN];
    __shared__ int   toks[BM];
    __shared__ float gws[BM];

    int tid = threadIdx.x;
    if (tid < BM) {
        int r = rowBase + tid;
        int rc = min(r, n_e - 1);
        toks[tid] = g_tok[e * T_TOK + rc];
        gws [tid] = g_gw [e * T_TOK + rc];
    }
    __syncthreads();

    int lm = tid >> 2;
    int lk = (tid & 3) * 4;
    int arow = min(rowBase + lm, n_e - 1);
    const float* hrow  = g_H + (size_t)arow * F_DIM + lk;
    const float* w2row = W2 + (size_t)(colBase + lm) * F_DIM + lk;

    int ty4 = (tid >> 4) * 4;
    int tx4 = (tid & 15) * 4;

    float acc[4][4] = {};

    for (int k0 = 0; k0 < F_DIM; k0 += BK) {
        float4 av = *(const float4*)(hrow  + k0);
        float4 bv = *(const float4*)(w2row + k0);
        As[lk + 0][lm] = av.x; As[lk + 1][lm] = av.y;
        As[lk + 2][lm] = av.z; As[lk + 3][lm] = av.w;
        Bs[lk + 0][lm] = bv.x; Bs[lk + 1][lm] = bv.y;
        Bs[lk + 2][lm] = bv.z; Bs[lk + 3][lm] = bv.w;
        __syncthreads();

#pragma unroll
        for (int k = 0; k < BK; k++) {
            float4 a = *(const float4*)&As[k][ty4];
            float4 b = *(const float4*)&Bs[k][tx4];
            float ax[4] = {a.x, a.y, a.z, a.w};
            float bx[4] = {b.x, b.y, b.z, b.w};
#pragma unroll
            for (int i = 0; i < 4; i++)
#pragma unroll
                for (int j = 0; j < 4; j++)
                    acc[i][j] = fmaf(ax[i], bx[j], acc[i][j]);
        }
        __syncthreads();
    }

#pragma unroll
    for (int i = 0; i < 4; i++) {
        int r = rowBase + ty4 + i;
        if (r >= n_e) continue;
        int t  = toks[ty4 + i];
        float w = gws[ty4 + i];
        float* o = out + (size_t)t * D_DIM + colBase + tx4;
#pragma unroll
        for (int j = 0; j < 4; j++)
            atomicAdd(&o[j], w * acc[i][j]);
    }
}

// ---------------- launch ------------------------------------------------------
extern "C" void kernel_launch(void* const* d_in, const int* in_sizes, int n_in,
                              void* d_out, int out_size)
{
    const float* x   = (const float*)d_in[0];  // hidden_states [2,2048,1024]
    const float* gw  = (const float*)d_in[1];  // gate_w [8,1024]
    const float* w1  = (const float*)d_in[2];  // [8,4096,1024]
    const float* w3  = (const float*)d_in[3];  // [8,4096,1024]
    const float* w2  = (const float*)d_in[4];  // [8,1024,4096]
    float* out = (float*)d_out;

    router_kernel<<<T_TOK / 4, 128>>>(x, gw);
    bucket_kernel<<<1, 32>>>();
    cudaMemsetAsync(d_out, 0, (size_t)out_size * sizeof(float));

    for (int e = 0; e < E_NUM; e++) {
        dim3 g1(F_DIM / BN, T_TOK / BM);
        gemm1_kernel<<<g1, 256>>>(x, w1, w3, e);
        dim3 g2(D_DIM / BN, T_TOK / BM);
        gemm2_kernel<<<g2, 256>>>(w2, out, e);
    }
}

// round 3
// speedup vs baseline: 5.0341x; 5.0341x over previous
#include <cuda_runtime.h>
#include <math.h>
#include <stdint.h>

// Problem constants: B=2, S=2048 -> T=4096 tokens, D=1024, F=4096, E=8, top-2
#define T_TOK 4096
#define D_DIM 1024
#define F_DIM 4096
#define E_NUM 8

// tiles
#define BM 128
#define BN 128
#define BK 32
#define PAD_ROW 36              // floats per smem row (32 + 4 pad)
#define TILE_FLOATS (BM * PAD_ROW)   // 4608 floats = 18432 bytes per tile buffer

// ---------------------------------------------------------------------------
// helpers
// ---------------------------------------------------------------------------
__device__ __forceinline__ uint32_t smem_to_u32(const void* p) {
    uint32_t a;
    asm("{ .reg .u64 t; cvta.to.shared.u64 t, %1; cvt.u32.u64 %0, t; }" : "=r"(a) : "l"(p));
    return a;
}
__device__ __forceinline__ uint32_t f2tf(float x) {   // round-to-nearest tf32
    uint32_t r;
    asm("cvt.rna.tf32.f32 %0, %1;" : "=r"(r) : "f"(x));
    return r;
}
__device__ __forceinline__ void mma8(float* c, const uint32_t* a, uint32_t b0, uint32_t b1) {
    asm volatile(
        "mma.sync.aligned.m16n8k8.row.col.f32.tf32.tf32.f32 "
        "{%0,%1,%2,%3}, {%4,%5,%6,%7}, {%8,%9}, {%0,%1,%2,%3};"
        : "+f"(c[0]), "+f"(c[1]), "+f"(c[2]), "+f"(c[3])
        : "r"(a[0]), "r"(a[1]), "r"(a[2]), "r"(a[3]), "r"(b0), "r"(b1));
}
#define CP_ASYNC16(dst, src) \
    asm volatile("cp.async.cg.shared.global [%0], [%1], 16;" :: "r"(dst), "l"(src) : "memory")
#define CP_COMMIT() asm volatile("cp.async.commit_group;" ::: "memory")
#define CP_WAIT1()  asm volatile("cp.async.wait_group 1;" ::: "memory")
#define CP_WAIT0()  asm volatile("cp.async.wait_group 0;" ::: "memory")

// ---------------------------------------------------------------------------
// scratch
// ---------------------------------------------------------------------------
__device__ int   g_sel[T_TOK * 2];
__device__ float g_wt [T_TOK * 2];
__device__ int   g_cnt[E_NUM];
__device__ int   g_tok[E_NUM * T_TOK];
__device__ float g_gw [E_NUM * T_TOK];
__device__ float g_H  [(size_t)(2 * T_TOK) * F_DIM];   // compacted intermediate, 128 MB

// ---------------------------------------------------------------------------
// router: logits -> softmax -> top2 -> renorm
// ---------------------------------------------------------------------------
__global__ void router_kernel(const float* __restrict__ x,
                              const float* __restrict__ gatew)
{
    int warp = threadIdx.x >> 5;
    int lane = threadIdx.x & 31;
    int t = blockIdx.x * 4 + warp;
    if (t >= T_TOK) return;
    const float* xr = x + (size_t)t * D_DIM;

    float acc[E_NUM];
#pragma unroll
    for (int e = 0; e < E_NUM; e++) acc[e] = 0.f;
    for (int d = lane; d < D_DIM; d += 32) {
        float xv = xr[d];
#pragma unroll
        for (int e = 0; e < E_NUM; e++)
            acc[e] = fmaf(xv, gatew[e * D_DIM + d], acc[e]);
    }
#pragma unroll
    for (int e = 0; e < E_NUM; e++) {
#pragma unroll
        for (int off = 16; off; off >>= 1)
            acc[e] += __shfl_xor_sync(0xffffffffu, acc[e], off);
    }
    if (lane == 0) {
        float m = acc[0];
#pragma unroll
        for (int e = 1; e < E_NUM; e++) m = fmaxf(m, acc[e]);
        float p[E_NUM];
#pragma unroll
        for (int e = 0; e < E_NUM; e++) p[e] = expf(acc[e] - m);
        int e0 = 0;
#pragma unroll
        for (int e = 1; e < E_NUM; e++) if (p[e] > p[e0]) e0 = e;
        int e1 = (e0 == 0) ? 1 : 0;
#pragma unroll
        for (int e = 0; e < E_NUM; e++) {
            if (e == e0) continue;
            if (p[e] > p[e1]) e1 = e;
        }
        float s = p[e0] + p[e1];
        g_sel[t * 2 + 0] = e0;
        g_sel[t * 2 + 1] = e1;
        g_wt [t * 2 + 0] = p[e0] / s;
        g_wt [t * 2 + 1] = p[e1] / s;
    }
}

// ---------------------------------------------------------------------------
// deterministic parallel bucket (counting sort)
// ---------------------------------------------------------------------------
__global__ __launch_bounds__(1024)
void bucket_kernel()
{
    __shared__ int cnt[E_NUM * 1024];
    int tid = threadIdx.x;
    int base = tid * 8;

    int sel[8];
#pragma unroll
    for (int j = 0; j < 8; j++) sel[j] = g_sel[base + j];

#pragma unroll
    for (int e = 0; e < E_NUM; e++) cnt[e * 1024 + tid] = 0;
    __syncthreads();
#pragma unroll
    for (int j = 0; j < 8; j++) cnt[sel[j] * 1024 + tid]++;
    __syncthreads();

    for (int d = 1; d < 1024; d <<= 1) {
        int v[E_NUM];
#pragma unroll
        for (int e = 0; e < E_NUM; e++)
            v[e] = (tid >= d) ? cnt[e * 1024 + tid - d] : 0;
        __syncthreads();
#pragma unroll
        for (int e = 0; e < E_NUM; e++) cnt[e * 1024 + tid] += v[e];
        __syncthreads();
    }
    if (tid < E_NUM) g_cnt[tid] = cnt[tid * 1024 + 1023];

#pragma unroll
    for (int j = 0; j < 8; j++) {
        int ex = sel[j];
        int prior = 0;
#pragma unroll
        for (int jj = 0; jj < 8; jj++)
            if (jj < j && sel[jj] == ex) prior++;
        int start = (tid > 0) ? cnt[ex * 1024 + tid - 1] : 0;
        int pos = start + prior;
        int slot = base + j;
        g_tok[ex * T_TOK + pos] = slot >> 1;
        g_gw [ex * T_TOK + pos] = g_wt[slot];
    }
}

// ---------------------------------------------------------------------------
// GEMM1: H = silu(X W1^T) * (X W3^T)  — tf32 mma.sync, 128x128x32 tiles
// smem: [2 buf][A | B1 | B3], each tile BM x PAD_ROW floats
// ---------------------------------------------------------------------------
#define G1_SMEM (6 * TILE_FLOATS * 4)    // 110592 bytes
#define G2_SMEM (4 * TILE_FLOATS * 4)    // 73728 bytes

__global__ __launch_bounds__(512)
void gemm1_tc(const float* __restrict__ x,
              const float* __restrict__ w1,
              const float* __restrict__ w3)
{
    int e = blockIdx.z;
    int n_e = g_cnt[e];
    int rowBase = blockIdx.y * BM;
    if (rowBase >= n_e) return;
    int colBase = blockIdx.x * BN;
    int hoff = 0;
#pragma unroll
    for (int i = 0; i < E_NUM; i++) hoff += (i < e) ? g_cnt[i] : 0;

    extern __shared__ float smem[];
    float* sA  = smem;                    // [2][TILE_FLOATS]
    float* sB1 = smem + 2 * TILE_FLOATS;
    float* sB3 = smem + 4 * TILE_FLOATS;
    uint32_t aA  = smem_to_u32(sA);
    uint32_t aB1 = smem_to_u32(sB1);
    uint32_t aB3 = smem_to_u32(sB3);

    int tid = threadIdx.x;
    int wid = tid >> 5, lane = tid & 31;
    int wr = wid >> 2, wc = wid & 3;     // 4x4 warp grid, 32x32 warp tiles
    int g  = lane >> 2, tg = lane & 3;

    // loader: each thread handles rows r0, r0+64 at float4 segment `seg`
    int r0 = tid >> 3, r1 = r0 + 64, seg = tid & 7;
    int tok0 = g_tok[e * T_TOK + min(rowBase + r0, n_e - 1)];
    int tok1 = g_tok[e * T_TOK + min(rowBase + r1, n_e - 1)];
    const float* srcA0 = x + (size_t)tok0 * D_DIM + seg * 4;
    const float* srcA1 = x + (size_t)tok1 * D_DIM + seg * 4;
    const float* srcB10 = w1 + ((size_t)e * F_DIM + colBase + r0) * D_DIM + seg * 4;
    const float* srcB11 = w1 + ((size_t)e * F_DIM + colBase + r1) * D_DIM + seg * 4;
    const float* srcB30 = w3 + ((size_t)e * F_DIM + colBase + r0) * D_DIM + seg * 4;
    const float* srcB31 = w3 + ((size_t)e * F_DIM + colBase + r1) * D_DIM + seg * 4;
    uint32_t dA0 = aA  + r0 * (PAD_ROW * 4) + seg * 16;
    uint32_t dA1 = aA  + r1 * (PAD_ROW * 4) + seg * 16;
    uint32_t dB10 = aB1 + r0 * (PAD_ROW * 4) + seg * 16;
    uint32_t dB11 = aB1 + r1 * (PAD_ROW * 4) + seg * 16;
    uint32_t dB30 = aB3 + r0 * (PAD_ROW * 4) + seg * 16;
    uint32_t dB31 = aB3 + r1 * (PAD_ROW * 4) + seg * 16;

#define G1_LOAD(b, kt) do {                                           \
        uint32_t bo = (uint32_t)(b) * (TILE_FLOATS * 4);              \
        size_t ko = (size_t)(kt) * BK;                                \
        CP_ASYNC16(dA0  + bo, srcA0  + ko);                           \
        CP_ASYNC16(dA1  + bo, srcA1  + ko);                           \
        CP_ASYNC16(dB10 + bo, srcB10 + ko);                           \
        CP_ASYNC16(dB11 + bo, srcB11 + ko);                           \
        CP_ASYNC16(dB30 + bo, srcB30 + ko);                           \
        CP_ASYNC16(dB31 + bo, srcB31 + ko);                           \
        CP_COMMIT();                                                  \
    } while (0)

    // fragment offsets (float units)
    int aoff0 = (wr * 32 + g) * PAD_ROW + tg;
    int aoff1 = aoff0 + 16 * PAD_ROW;
    int boff[4];
#pragma unroll
    for (int nt = 0; nt < 4; nt++) boff[nt] = (wc * 32 + nt * 8 + g) * PAD_ROW + tg;

    float acc1[2][4][4] = {};
    float acc3[2][4][4] = {};

    const int NK = D_DIM / BK;   // 32
    G1_LOAD(0, 0);

#pragma unroll 1
    for (int kt = 0; kt < NK; kt++) {
        int b = kt & 1;
        if (kt + 1 < NK) { G1_LOAD((kt + 1) & 1, kt + 1); CP_WAIT1(); }
        else             { CP_WAIT0(); }
        __syncthreads();

        const float* pA  = sA  + b * TILE_FLOATS;
        const float* pB1 = sB1 + b * TILE_FLOATS;
        const float* pB3 = sB3 + b * TILE_FLOATS;
#pragma unroll
        for (int s = 0; s < 4; s++) {
            int ks = s * 8;
            uint32_t af[2][4];
            const float* a0p = pA + aoff0 + ks;
            const float* a1p = pA + aoff1 + ks;
            af[0][0] = f2tf(a0p[0]);            af[0][1] = f2tf(a0p[8 * PAD_ROW]);
            af[0][2] = f2tf(a0p[4]);            af[0][3] = f2tf(a0p[8 * PAD_ROW + 4]);
            af[1][0] = f2tf(a1p[0]);            af[1][1] = f2tf(a1p[8 * PAD_ROW]);
            af[1][2] = f2tf(a1p[4]);            af[1][3] = f2tf(a1p[8 * PAD_ROW + 4]);
#pragma unroll
            for (int nt = 0; nt < 4; nt++) {
                const float* bp1 = pB1 + boff[nt] + ks;
                uint32_t b0 = f2tf(bp1[0]), b1 = f2tf(bp1[4]);
                mma8(acc1[0][nt], af[0], b0, b1);
                mma8(acc1[1][nt], af[1], b0, b1);
                const float* bp3 = pB3 + boff[nt] + ks;
                uint32_t c0 = f2tf(bp3[0]), c1 = f2tf(bp3[4]);
                mma8(acc3[0][nt], af[0], c0, c1);
                mma8(acc3[1][nt], af[1], c0, c1);
            }
        }
        __syncthreads();
    }

    // epilogue: silu(acc1)*acc3 -> g_H
#pragma unroll
    for (int mt = 0; mt < 2; mt++) {
        int rl0 = rowBase + wr * 32 + mt * 16 + g;
#pragma unroll
        for (int nt = 0; nt < 4; nt++) {
            int col = colBase + wc * 32 + nt * 8 + tg * 2;
            const float* c1 = acc1[mt][nt];
            const float* c3 = acc3[mt][nt];
            if (rl0 < n_e) {
                float v0 = c1[0], v1 = c1[1];
                float2 o;
                o.x = v0 / (1.f + expf(-v0)) * c3[0];
                o.y = v1 / (1.f + expf(-v1)) * c3[1];
                *(float2*)(g_H + (size_t)(hoff + rl0) * F_DIM + col) = o;
            }
            int rl1 = rl0 + 8;
            if (rl1 < n_e) {
                float v2 = c1[2], v3 = c1[3];
                float2 o;
                o.x = v2 / (1.f + expf(-v2)) * c3[2];
                o.y = v3 / (1.f + expf(-v3)) * c3[3];
                *(float2*)(g_H + (size_t)(hoff + rl1) * F_DIM + col) = o;
            }
        }
    }
}

// ---------------------------------------------------------------------------
// GEMM2: out[tok] += gw * (H W2^T)  — tf32 mma.sync, K = F_DIM
// ---------------------------------------------------------------------------
__global__ __launch_bounds__(512)
void gemm2_tc(const float* __restrict__ w2,
              float* __restrict__ out)
{
    int e = blockIdx.z;
    int n_e = g_cnt[e];
    int rowBase = blockIdx.y * BM;
    if (rowBase >= n_e) return;
    int colBase = blockIdx.x * BN;    // over D
    int hoff = 0;
#pragma unroll
    for (int i = 0; i < E_NUM; i++) hoff += (i < e) ? g_cnt[i] : 0;

    extern __shared__ float smem[];
    float* sA = smem;                  // [2][TILE_FLOATS]
    float* sB = smem + 2 * TILE_FLOATS;
    uint32_t aA = smem_to_u32(sA);
    uint32_t aB = smem_to_u32(sB);

    int tid = threadIdx.x;
    int wid = tid >> 5, lane = tid & 31;
    int wr = wid >> 2, wc = wid & 3;
    int g  = lane >> 2, tg = lane & 3;

    int r0 = tid >> 3, r1 = r0 + 64, seg = tid & 7;
    const float* srcA0 = g_H + (size_t)(hoff + min(rowBase + r0, n_e - 1)) * F_DIM + seg * 4;
    const float* srcA1 = g_H + (size_t)(hoff + min(rowBase + r1, n_e - 1)) * F_DIM + seg * 4;
    const float* srcB0 = w2 + ((size_t)e * D_DIM + colBase + r0) * F_DIM + seg * 4;
    const float* srcB1 = w2 + ((size_t)e * D_DIM + colBase + r1) * F_DIM + seg * 4;
    uint32_t dA0 = aA + r0 * (PAD_ROW * 4) + seg * 16;
    uint32_t dA1 = aA + r1 * (PAD_ROW * 4) + seg * 16;
    uint32_t dB0 = aB + r0 * (PAD_ROW * 4) + seg * 16;
    uint32_t dB1 = aB + r1 * (PAD_ROW * 4) + seg * 16;

#define G2_LOAD(b, kt) do {                                           \
        uint32_t bo = (uint32_t)(b) * (TILE_FLOATS * 4);              \
        size_t ko = (size_t)(kt) * BK;                                \
        CP_ASYNC16(dA0 + bo, srcA0 + ko);                             \
        CP_ASYNC16(dA1 + bo, srcA1 + ko);                             \
        CP_ASYNC16(dB0 + bo, srcB0 + ko);                             \
        CP_ASYNC16(dB1 + bo, srcB1 + ko);                             \
        CP_COMMIT();                                                  \
    } while (0)

    int aoff0 = (wr * 32 + g) * PAD_ROW + tg;
    int aoff1 = aoff0 + 16 * PAD_ROW;
    int boff[4];
#pragma unroll
    for (int nt = 0; nt < 4; nt++) boff[nt] = (wc * 32 + nt * 8 + g) * PAD_ROW + tg;

    float acc[2][4][4] = {};

    const int NK = F_DIM / BK;   // 128
    G2_LOAD(0, 0);

#pragma unroll 1
    for (int kt = 0; kt < NK; kt++) {
        int b = kt & 1;
        if (kt + 1 < NK) { G2_LOAD((kt + 1) & 1, kt + 1); CP_WAIT1(); }
        else             { CP_WAIT0(); }
        __syncthreads();

        const float* pA = sA + b * TILE_FLOATS;
        const float* pB = sB + b * TILE_FLOATS;
#pragma unroll
        for (int s = 0; s < 4; s++) {
            int ks = s * 8;
            uint32_t af[2][4];
            const float* a0p = pA + aoff0 + ks;
            const float* a1p = pA + aoff1 + ks;
            af[0][0] = f2tf(a0p[0]);            af[0][1] = f2tf(a0p[8 * PAD_ROW]);
            af[0][2] = f2tf(a0p[4]);            af[0][3] = f2tf(a0p[8 * PAD_ROW + 4]);
            af[1][0] = f2tf(a1p[0]);            af[1][1] = f2tf(a1p[8 * PAD_ROW]);
            af[1][2] = f2tf(a1p[4]);            af[1][3] = f2tf(a1p[8 * PAD_ROW + 4]);
#pragma unroll
            for (int nt = 0; nt < 4; nt++) {
                const float* bp = pB + boff[nt] + ks;
                uint32_t b0 = f2tf(bp[0]), b1 = f2tf(bp[4]);
                mma8(acc[0][nt], af[0], b0, b1);
                mma8(acc[1][nt], af[1], b0, b1);
            }
        }
        __syncthreads();
    }

    // epilogue: scatter with atomicAdd (token may be routed to 2 experts)
#pragma unroll
    for (int mt = 0; mt < 2; mt++) {
#pragma unroll
        for (int h = 0; h < 2; h++) {
            int rl = rowBase + wr * 32 + mt * 16 + g + h * 8;
            if (rl >= n_e) continue;
            int t  = g_tok[e * T_TOK + rl];
            float w = g_gw[e * T_TOK + rl];
            float* ob = out + (size_t)t * D_DIM + colBase + wc * 32;
#pragma unroll
            for (int nt = 0; nt < 4; nt++) {
                const float* c = acc[mt][nt];
                atomicAdd(&ob[nt * 8 + tg * 2 + 0], w * c[h * 2 + 0]);
                atomicAdd(&ob[nt * 8 + tg * 2 + 1], w * c[h * 2 + 1]);
            }
        }
    }
}

// ---------------------------------------------------------------------------
// launch
// ---------------------------------------------------------------------------
extern "C" void kernel_launch(void* const* d_in, const int* in_sizes, int n_in,
                              void* d_out, int out_size)
{
    const float* x  = (const float*)d_in[0];
    const float* gw = (const float*)d_in[1];
    const float* w1 = (const float*)d_in[2];
    const float* w3 = (const float*)d_in[3];
    const float* w2 = (const float*)d_in[4];
    float* out = (float*)d_out;

    cudaFuncSetAttribute(gemm1_tc, cudaFuncAttributeMaxDynamicSharedMemorySize, G1_SMEM);
    cudaFuncSetAttribute(gemm2_tc, cudaFuncAttributeMaxDynamicSharedMemorySize, G2_SMEM);

    router_kernel<<<T_TOK / 4, 128>>>(x, gw);
    bucket_kernel<<<1, 1024>>>();
    cudaMemsetAsync(d_out, 0, (size_t)out_size * sizeof(float));

    dim3 g1(F_DIM / BN, T_TOK / BM, E_NUM);   // 32 x 32 x 8 (early exit on empty)
    gemm1_tc<<<g1, 512, G1_SMEM>>>(x, w1, w3);

    dim3 g2(D_DIM / BN, T_TOK / BM, E_NUM);   // 8 x 32 x 8
    gemm2_tc<<<g2, 512, G2_SMEM>>>(w2, out);
}